// round 14
// baseline (speedup 1.0000x reference)
#include <cuda_runtime.h>
#include <cuda_fp16.h>
#include <cstdint>
#include <math.h>

#define BSZ   8192
#define IND   1024
#define OUTD  1024
#define NSPLIT 4
#define NCHUNK 512          // = number of fused-softmax blocks
#define RPB    16           // rows per fused-softmax block

// ---- scratch (static device globals; no dynamic allocation) ----
__device__ float    g_u  [(size_t)BSZ * OUTD];           // 32 MB
__device__ float    g_P  [NCHUNK * OUTD];
__device__ float    g_m  [OUTD];
__device__ float    g_rate[OUTD];
__device__ float    g_S  [(size_t)NSPLIT * OUTD * IND];  // 16 MB
// GEMM1 operands: bf16 hi/lo (K-major)
__device__ uint16_t g_xh [(size_t)BSZ * IND];
__device__ uint16_t g_xl [(size_t)BSZ * IND];
__device__ uint16_t g_Wh [(size_t)OUTD * IND];
__device__ uint16_t g_Wl [(size_t)OUTD * IND];
// GEMM2 operands: f16 (x^T single, yn^T hi/lo)
__device__ uint16_t g_xTh [(size_t)IND * BSZ];
__device__ uint16_t g_ynTh[(size_t)OUTD * BSZ];
__device__ uint16_t g_ynTl[(size_t)OUTD * BSZ];

// ============================================================
// helpers
// ============================================================
__device__ __forceinline__ uint32_t bf16x2_rn(float hi, float lo) {
    uint32_t r;
    asm("cvt.rn.bf16x2.f32 %0, %1, %2;" : "=r"(r) : "f"(hi), "f"(lo));
    return r;
}
__device__ __forceinline__ void mma_bf16_k16(float c[4], const uint32_t a[4],
                                             const uint32_t b[2])
{
    asm volatile(
        "mma.sync.aligned.m16n8k16.row.col.f32.bf16.bf16.f32 "
        "{%0,%1,%2,%3}, {%4,%5,%6,%7}, {%8,%9}, {%0,%1,%2,%3};\n"
        : "+f"(c[0]), "+f"(c[1]), "+f"(c[2]), "+f"(c[3])
        : "r"(a[0]), "r"(a[1]), "r"(a[2]), "r"(a[3]),
          "r"(b[0]), "r"(b[1]));
}
__device__ __forceinline__ void mma_f16_k16(float c[4], const uint32_t a[4],
                                            const uint32_t b[2])
{
    asm volatile(
        "mma.sync.aligned.m16n8k16.row.col.f32.f16.f16.f32 "
        "{%0,%1,%2,%3}, {%4,%5,%6,%7}, {%8,%9}, {%0,%1,%2,%3};\n"
        : "+f"(c[0]), "+f"(c[1]), "+f"(c[2]), "+f"(c[3])
        : "r"(a[0]), "r"(a[1]), "r"(a[2]), "r"(a[3]),
          "r"(b[0]), "r"(b[1]));
}
__device__ __forceinline__ void ldsm_x4(uint32_t r[4], uint32_t addr) {
    asm volatile("ldmatrix.sync.aligned.m8n8.x4.shared.b16 {%0,%1,%2,%3}, [%4];"
        : "=r"(r[0]), "=r"(r[1]), "=r"(r[2]), "=r"(r[3]) : "r"(addr));
}
#define CP_ASYNC16(saddr, gptr) \
    asm volatile("cp.async.cg.shared.global [%0], [%1], 16;" \
        :: "r"(saddr), "l"(gptr))
// .noinc: arrive WITHOUT bumping expected-count (barrier inited to NTHREADS).
#define CP_MBAR_ARRIVE(mbar) \
    asm volatile("cp.async.mbarrier.arrive.noinc.shared::cta.b64 [%0];" \
        :: "r"((uint32_t)(mbar)) : "memory")
#define MBARRIER_INIT(mbar, cnt) \
    asm volatile("mbarrier.init.shared.b64 [%0], %1;" \
        :: "r"((uint32_t)(mbar)), "r"((uint32_t)(cnt)) : "memory")
#define MBARRIER_ARRIVE(mbar) \
    asm volatile("mbarrier.arrive.shared::cta.b64 _, [%0];" \
        :: "r"((uint32_t)(mbar)) : "memory")
#define MBARRIER_WAIT_PARITY(mbar, parity) do {                                   \
    uint32_t _m = (uint32_t)(mbar); uint32_t _p = (uint32_t)(parity);             \
    uint32_t _done;                                                               \
    asm volatile("{\n\t.reg .pred p;\n\t"                                         \
        "mbarrier.try_wait.parity.acquire.cta.shared::cta.b64 p, [%1], %2;\n\t"   \
        "selp.b32 %0, 1, 0, p;\n\t}" : "=r"(_done) : "r"(_m), "r"(_p) : "memory");\
    if (!_done) {                                                                 \
        asm volatile("{\n\t.reg .pred P1;\n\t"                                    \
            "WL_%=:\n\t"                                                          \
            "mbarrier.try_wait.parity.acquire.cta.shared::cta.b64 P1, [%0], %1, 0x989680;\n\t" \
            "@P1 bra.uni WD_%=;\n\t"                                              \
            "bra.uni WL_%=;\n\t"                                                  \
            "WD_%=:\n\t}" :: "r"(_m), "r"(_p) : "memory");                        \
    }                                                                             \
} while (0)

// Common geometry
#define BK      32
#define BM      256
#define BN      128
#define STRIDE  40
#define NTHREADS 512

// ---- GEMM1 (bf16 3-pass) stage layout, 3-slot ring ----
#define NSTAGE1 3
#define SM_AH   0
#define SM_AL   (BM * STRIDE * 2)                          // 20480
#define SM_BH   (2 * BM * STRIDE * 2)                      // 40960
#define SM_BL   (2 * BM * STRIDE * 2 + BN * STRIDE * 2)    // 51200
#define STAGE_B (2 * BM * STRIDE * 2 + 2 * BN * STRIDE * 2) // 61440
#define SM_BARS (NSTAGE1 * STAGE_B)                        // 184320
#define SMEM_BYTES (SM_BARS + 64)

// ---- GEMM2 (f16 2-pass) stage layout: Ah, Al, Bh; 4-slot ring ----
#define NSTAGE2 4
#define P2_AH    0
#define P2_AL    (BM * STRIDE * 2)                         // 20480
#define P2_BH    (2 * BM * STRIDE * 2)                     // 40960
#define STAGE2_B (2 * BM * STRIDE * 2 + BN * STRIDE * 2)   // 51200
#define SM2_BARS (NSTAGE2 * STAGE2_B)                      // 204800
#define SMEM2_BYTES (SM2_BARS + 64)

// ============================================================
// fill helpers
// ============================================================
__device__ __forceinline__ void fill_stage3(
    uint32_t sbase, int t,
    const uint16_t* __restrict__ Ah, const uint16_t* __restrict__ Al, int lda,
    const uint16_t* __restrict__ Bh, const uint16_t* __restrict__ Bl, int ldb,
    int m0, int n0, int ks0)
{
#pragma unroll
    for (int i = 0; i < 2; ++i) {
        const int c   = t + 512 * i;
        const int row = c >> 2;
        const int c16 = c & 3;
        const size_t go = (size_t)(m0 + row) * lda + ks0 + c16 * 8;
        const uint32_t so = (uint32_t)((row * STRIDE + c16 * 8) * 2);
        CP_ASYNC16(sbase + SM_AH + so, Ah + go);
        CP_ASYNC16(sbase + SM_AL + so, Al + go);
    }
    {
        const int row = t >> 2;
        const int c16 = t & 3;
        const size_t go = (size_t)(n0 + row) * ldb + ks0 + c16 * 8;
        const uint32_t so = (uint32_t)((row * STRIDE + c16 * 8) * 2);
        CP_ASYNC16(sbase + SM_BH + so, Bh + go);
        CP_ASYNC16(sbase + SM_BL + so, Bl + go);
    }
}

__device__ __forceinline__ void fill_stage2(
    uint32_t sbase, int t,
    const uint16_t* __restrict__ Ah, const uint16_t* __restrict__ Al, int lda,
    const uint16_t* __restrict__ Bh, int ldb,
    int m0, int n0, int ks0)
{
#pragma unroll
    for (int i = 0; i < 2; ++i) {
        const int c   = t + 512 * i;
        const int row = c >> 2;
        const int c16 = c & 3;
        const size_t go = (size_t)(m0 + row) * lda + ks0 + c16 * 8;
        const uint32_t so = (uint32_t)((row * STRIDE + c16 * 8) * 2);
        CP_ASYNC16(sbase + P2_AH + so, Ah + go);
        CP_ASYNC16(sbase + P2_AL + so, Al + go);
    }
    {
        const int row = t >> 2;
        const int c16 = t & 3;
        const size_t go = (size_t)(n0 + row) * ldb + ks0 + c16 * 8;
        const uint32_t so = (uint32_t)((row * STRIDE + c16 * 8) * 2);
        CP_ASYNC16(sbase + P2_BH + so, Bh + go);
    }
}

// ============================================================
// GEMM1: bf16x3 mma.sync with mbarrier full/empty ring (R11 design).
// CTA 256x128, 512 thr / 16 warps (4M x 4N), warp tile 64x32.
// ============================================================
__global__ __launch_bounds__(NTHREADS, 1) void gemm_bf16v5_kernel(
    const uint16_t* __restrict__ Ah, const uint16_t* __restrict__ Al, int lda,
    const uint16_t* __restrict__ Bh, const uint16_t* __restrict__ Bl, int ldb,
    int kzstep, float* __restrict__ dstBase, int ldd, size_t zstride,
    const float* __restrict__ bias, int nstages)
{
    extern __shared__ uint16_t sm[];
    const uint32_t sbase0 = (uint32_t)__cvta_generic_to_shared(sm);
    const uint32_t barF = sbase0 + SM_BARS;
    const uint32_t barE = sbase0 + SM_BARS + NSTAGE1 * 8;

    const int t     = threadIdx.x;
    const int lane  = t & 31;
    const int warp  = t >> 5;
    const int warpM = warp & 3;
    const int warpN = warp >> 2;
    const int m0    = blockIdx.y * BM;
    const int n0    = blockIdx.x * BN;
    const int kbase = blockIdx.z * kzstep;
    float* dst = dstBase + (size_t)blockIdx.z * zstride;

    const int gr   = lane >> 2;
    const int la15 = lane & 15;
    const int lhi  = lane >> 4;

    uint32_t aoff[4], boff[2];
#pragma unroll
    for (int mt = 0; mt < 4; ++mt)
        aoff[mt] = (uint32_t)(((warpM * 64 + mt * 16 + la15) * STRIDE
                               + lhi * 8) * 2);
#pragma unroll
    for (int p = 0; p < 2; ++p)
        boff[p] = (uint32_t)(((warpN * 32 + p * 16 + lhi * 8 + (lane & 7))
                               * STRIDE + ((lane >> 3) & 1) * 8) * 2);

    if (t == 0) {
#pragma unroll
        for (int j = 0; j < NSTAGE1; ++j) {
            MBARRIER_INIT(barF + j * 8, NTHREADS);
            MBARRIER_INIT(barE + j * 8, NTHREADS);
        }
    }
    __syncthreads();

    float c[4][4][4];
#pragma unroll
    for (int mt = 0; mt < 4; ++mt)
#pragma unroll
        for (int nt = 0; nt < 4; ++nt)
#pragma unroll
            for (int e = 0; e < 4; ++e) c[mt][nt][e] = 0.f;

    fill_stage3(sbase0, t, Ah, Al, lda, Bh, Bl, ldb, m0, n0, kbase);
    CP_MBAR_ARRIVE(barF);

    int fs = 1, pslot = 1, pph = 0;
    int cslot = 0, cph = 0;

    for (int s = 0; s < nstages; ++s) {
        if (fs < nstages) {
            if (fs >= NSTAGE1)
                MBARRIER_WAIT_PARITY(barE + pslot * 8, pph ^ 1);
            fill_stage3(sbase0 + pslot * STAGE_B, t, Ah, Al, lda, Bh, Bl, ldb,
                        m0, n0, kbase + fs * BK);
            CP_MBAR_ARRIVE(barF + pslot * 8);
            ++fs;
            if (++pslot == NSTAGE1) { pslot = 0; pph ^= 1; }
        }

        MBARRIER_WAIT_PARITY(barF + cslot * 8, cph);
        const uint32_t sb  = sbase0 + cslot * STAGE_B;
        const uint32_t sAh = sb + SM_AH;
        const uint32_t sAl = sb + SM_AL;
        const uint32_t sBh = sb + SM_BH;
        const uint32_t sBl = sb + SM_BL;

#pragma unroll
        for (int ks = 0; ks < 2; ++ks) {
            const uint32_t ko = (uint32_t)(ks * 32);
            uint32_t ah[4][4], bb[4][2], t4[4];

#pragma unroll
            for (int mt = 0; mt < 4; ++mt)
                ldsm_x4(ah[mt], sAh + aoff[mt] + ko);
#pragma unroll
            for (int p = 0; p < 2; ++p) {
                ldsm_x4(t4, sBh + boff[p] + ko);
                bb[2*p][0] = t4[0]; bb[2*p][1] = t4[1];
                bb[2*p+1][0] = t4[2]; bb[2*p+1][1] = t4[3];
            }
#pragma unroll
            for (int mt = 0; mt < 4; ++mt)
#pragma unroll
                for (int nt = 0; nt < 4; ++nt)
                    mma_bf16_k16(c[mt][nt], ah[mt], bb[nt]);
            {
                uint32_t bl[4][2];
#pragma unroll
                for (int p = 0; p < 2; ++p) {
                    ldsm_x4(t4, sBl + boff[p] + ko);
                    bl[2*p][0] = t4[0]; bl[2*p][1] = t4[1];
                    bl[2*p+1][0] = t4[2]; bl[2*p+1][1] = t4[3];
                }
#pragma unroll
                for (int mt = 0; mt < 4; ++mt)
#pragma unroll
                    for (int nt = 0; nt < 4; ++nt)
                        mma_bf16_k16(c[mt][nt], ah[mt], bl[nt]);
            }
            {
                uint32_t al[4][4];
#pragma unroll
                for (int mt = 0; mt < 4; ++mt)
                    ldsm_x4(al[mt], sAl + aoff[mt] + ko);
                if (ks == 1)
                    MBARRIER_ARRIVE(barE + cslot * 8);
#pragma unroll
                for (int mt = 0; mt < 4; ++mt)
#pragma unroll
                    for (int nt = 0; nt < 4; ++nt)
                        mma_bf16_k16(c[mt][nt], al[mt], bb[nt]);
            }
        }
        if (++cslot == NSTAGE1) { cslot = 0; cph ^= 1; }
    }

#pragma unroll
    for (int mt = 0; mt < 4; ++mt) {
        const int r = m0 + warpM * 64 + mt * 16 + gr;
#pragma unroll
        for (int nt = 0; nt < 4; ++nt) {
            const int cc = n0 + warpN * 32 + nt * 8 + (lane & 3) * 2;
            float2 v0 = make_float2(c[mt][nt][0], c[mt][nt][1]);
            float2 v1 = make_float2(c[mt][nt][2], c[mt][nt][3]);
            if (bias) {
                const float b0 = __ldg(&bias[cc]);
                const float b1 = __ldg(&bias[cc + 1]);
                v0.x += b0; v0.y += b1;
                v1.x += b0; v1.y += b1;
            }
            *reinterpret_cast<float2*>(&dst[(size_t)r * ldd + cc])       = v0;
            *reinterpret_cast<float2*>(&dst[(size_t)(r + 8) * ldd + cc]) = v1;
        }
    }
}

// ============================================================
// GEMM2: f16 2-pass (A = yn^T hi/lo f16, B = x^T f16 single), 4-slot ring.
// ============================================================
__global__ __launch_bounds__(NTHREADS, 1) void gemm_f16_2p_kernel(
    const uint16_t* __restrict__ Ah, const uint16_t* __restrict__ Al, int lda,
    const uint16_t* __restrict__ Bh, int ldb,
    int kzstep, float* __restrict__ dstBase, int ldd, size_t zstride,
    int nstages)
{
    extern __shared__ uint16_t sm[];
    const uint32_t sbase0 = (uint32_t)__cvta_generic_to_shared(sm);
    const uint32_t barF = sbase0 + SM2_BARS;
    const uint32_t barE = sbase0 + SM2_BARS + NSTAGE2 * 8;

    const int t     = threadIdx.x;
    const int lane  = t & 31;
    const int warp  = t >> 5;
    const int warpM = warp & 3;
    const int warpN = warp >> 2;
    const int m0    = blockIdx.y * BM;
    const int n0    = blockIdx.x * BN;
    const int kbase = blockIdx.z * kzstep;
    float* dst = dstBase + (size_t)blockIdx.z * zstride;

    const int gr   = lane >> 2;
    const int la15 = lane & 15;
    const int lhi  = lane >> 4;

    uint32_t aoff[4], boff[2];
#pragma unroll
    for (int mt = 0; mt < 4; ++mt)
        aoff[mt] = (uint32_t)(((warpM * 64 + mt * 16 + la15) * STRIDE
                               + lhi * 8) * 2);
#pragma unroll
    for (int p = 0; p < 2; ++p)
        boff[p] = (uint32_t)(((warpN * 32 + p * 16 + lhi * 8 + (lane & 7))
                               * STRIDE + ((lane >> 3) & 1) * 8) * 2);

    if (t == 0) {
#pragma unroll
        for (int j = 0; j < NSTAGE2; ++j) {
            MBARRIER_INIT(barF + j * 8, NTHREADS);
            MBARRIER_INIT(barE + j * 8, NTHREADS);
        }
    }
    __syncthreads();

    float c[4][4][4];
#pragma unroll
    for (int mt = 0; mt < 4; ++mt)
#pragma unroll
        for (int nt = 0; nt < 4; ++nt)
#pragma unroll
            for (int e = 0; e < 4; ++e) c[mt][nt][e] = 0.f;

    fill_stage2(sbase0, t, Ah, Al, lda, Bh, ldb, m0, n0, kbase);
    CP_MBAR_ARRIVE(barF);

    int fs = 1, pslot = 1, pph = 0;
    int cslot = 0, cph = 0;

    for (int s = 0; s < nstages; ++s) {
        if (fs < nstages) {
            if (fs >= NSTAGE2)
                MBARRIER_WAIT_PARITY(barE + pslot * 8, pph ^ 1);
            fill_stage2(sbase0 + pslot * STAGE2_B, t, Ah, Al, lda, Bh, ldb,
                        m0, n0, kbase + fs * BK);
            CP_MBAR_ARRIVE(barF + pslot * 8);
            ++fs;
            if (++pslot == NSTAGE2) { pslot = 0; pph ^= 1; }
        }

        MBARRIER_WAIT_PARITY(barF + cslot * 8, cph);
        const uint32_t sb  = sbase0 + cslot * STAGE2_B;
        const uint32_t sAh = sb + P2_AH;
        const uint32_t sAl = sb + P2_AL;
        const uint32_t sBh = sb + P2_BH;

#pragma unroll
        for (int ks = 0; ks < 2; ++ks) {
            const uint32_t ko = (uint32_t)(ks * 32);
            uint32_t ah[4][4], bb[4][2], t4[4];

#pragma unroll
            for (int mt = 0; mt < 4; ++mt)
                ldsm_x4(ah[mt], sAh + aoff[mt] + ko);
#pragma unroll
            for (int p = 0; p < 2; ++p) {
                ldsm_x4(t4, sBh + boff[p] + ko);
                bb[2*p][0] = t4[0]; bb[2*p][1] = t4[1];
                bb[2*p+1][0] = t4[2]; bb[2*p+1][1] = t4[3];
            }
#pragma unroll
            for (int mt = 0; mt < 4; ++mt)
#pragma unroll
                for (int nt = 0; nt < 4; ++nt)
                    mma_f16_k16(c[mt][nt], ah[mt], bb[nt]);
            {
                uint32_t al[4][4];
#pragma unroll
                for (int mt = 0; mt < 4; ++mt)
                    ldsm_x4(al[mt], sAl + aoff[mt] + ko);
                if (ks == 1)
                    MBARRIER_ARRIVE(barE + cslot * 8);
#pragma unroll
                for (int mt = 0; mt < 4; ++mt)
#pragma unroll
                    for (int nt = 0; nt < 4; ++nt)
                        mma_f16_k16(c[mt][nt], al[mt], bb[nt]);
            }
        }
        if (++cslot == NSTAGE2) { cslot = 0; cph ^= 1; }
    }

#pragma unroll
    for (int mt = 0; mt < 4; ++mt) {
        const int r = m0 + warpM * 64 + mt * 16 + gr;
#pragma unroll
        for (int nt = 0; nt < 4; ++nt) {
            const int cc = n0 + warpN * 32 + nt * 8 + (lane & 3) * 2;
            *reinterpret_cast<float2*>(&dst[(size_t)r * ldd + cc]) =
                make_float2(c[mt][nt][0], c[mt][nt][1]);
            *reinterpret_cast<float2*>(&dst[(size_t)(r + 8) * ldd + cc]) =
                make_float2(c[mt][nt][2], c[mt][nt][3]);
        }
    }
}

// ============================================================
// Fused x prep: read x once -> bf16 hi/lo row-major + x^T f16
// ============================================================
__global__ __launch_bounds__(256) void xprep_kernel(
    const float* __restrict__ src, uint16_t* __restrict__ dh,
    uint16_t* __restrict__ dl, uint16_t* __restrict__ dT, int R, int C)
{
    __shared__ float tile[32][33];
    const int c0 = blockIdx.x * 32;
    const int r0 = blockIdx.y * 32;
    const int tx = threadIdx.x, ty = threadIdx.y;
#pragma unroll
    for (int i = 0; i < 4; ++i) {
        const size_t o = (size_t)(r0 + ty + i*8) * C + c0 + tx;
        float v = src[o];
        tile[ty + i*8][tx] = v;
        uint32_t u = __float_as_uint(v);
        float lo = v - __uint_as_float(u & 0xFFFF0000u);
        dh[o] = (uint16_t)(u >> 16);
        dl[o] = (uint16_t)(bf16x2_rn(lo, lo) & 0xFFFF);
    }
    __syncthreads();
#pragma unroll
    for (int i = 0; i < 4; ++i) {
        __half h = __float2half_rn(tile[tx][ty + i*8]);
        dT[(size_t)(c0 + ty + i*8) * R + r0 + tx] = __half_as_ushort(h);
    }
}

// ============================================================
// Fused W prep: read W once -> bf16 hi/lo + adaptive rate
// ============================================================
__global__ __launch_bounds__(256) void wprep_kernel(
    const float* __restrict__ W, uint16_t* __restrict__ dh,
    uint16_t* __restrict__ dl)
{
    const int o = blockIdx.x;
    const int t = threadIdx.x;
    const unsigned full = 0xffffffffu;
    float4 v = reinterpret_cast<const float4*>(&W[(size_t)o * IND])[t];

    uint32_t x0 = __float_as_uint(v.x), x1 = __float_as_uint(v.y);
    uint32_t x2 = __float_as_uint(v.z), x3 = __float_as_uint(v.w);
    float l0 = v.x - __uint_as_float(x0 & 0xFFFF0000u);
    float l1 = v.y - __uint_as_float(x1 & 0xFFFF0000u);
    float l2 = v.z - __uint_as_float(x2 & 0xFFFF0000u);
    float l3 = v.w - __uint_as_float(x3 & 0xFFFF0000u);
    reinterpret_cast<uint2*>(dh)[(size_t)o * (IND/4) + t] =
        make_uint2(__byte_perm(x0, x1, 0x7632), __byte_perm(x2, x3, 0x7632));
    reinterpret_cast<uint2*>(dl)[(size_t)o * (IND/4) + t] =
        make_uint2(bf16x2_rn(l1, l0), bf16x2_rn(l3, l2));

    float s = v.x*v.x + v.y*v.y + v.z*v.z + v.w*v.w;
#pragma unroll
    for (int off = 16; off > 0; off >>= 1) s += __shfl_down_sync(full, s, off);
    __shared__ float ssum[8];
    const int warp = t >> 5, lane = t & 31;
    if (lane == 0) ssum[warp] = s;
    __syncthreads();
    if (t == 0) {
        float tot = 0.f;
        for (int w2 = 0; w2 < 8; ++w2) tot += ssum[w2];
        g_rate[o] = 1e-3f * sqrtf(fabsf(1.f - sqrtf(tot)));
    }
}

// ============================================================
// Fused softmax: per 16-row slab — softmax + negate + yn^T f16 hi/lo
// (transposed write) + m-partials. Eliminates fp32 yn entirely.
// ============================================================
__global__ __launch_bounds__(256) void softmax_fused_kernel(
    uint16_t* __restrict__ ynTh, uint16_t* __restrict__ ynTl)
{
    __shared__ uint16_t snh[RPB][1032];
    __shared__ uint16_t snl[RPB][1032];
    __shared__ float smx[8];
    __shared__ int   sai[8];
    __shared__ float ssum[8];

    const int t = threadIdx.x;
    const int b0 = blockIdx.x * RPB;
    const int warp = t >> 5, lane = t & 31;
    const unsigned full = 0xffffffffu;

    float mAcc[4] = {0.f, 0.f, 0.f, 0.f};

    for (int r = 0; r < RPB; ++r) {
        float4 v = reinterpret_cast<const float4*>(
            &g_u[(size_t)(b0 + r) * OUTD])[t];

        float mx = v.x; int ai = t*4;
        if (v.y > mx) { mx = v.y; ai = t*4+1; }
        if (v.z > mx) { mx = v.z; ai = t*4+2; }
        if (v.w > mx) { mx = v.w; ai = t*4+3; }
#pragma unroll
        for (int off = 16; off > 0; off >>= 1) {
            float omx = __shfl_down_sync(full, mx, off);
            int   oai = __shfl_down_sync(full, ai, off);
            if (omx > mx || (omx == mx && oai < ai)) { mx = omx; ai = oai; }
        }
        if (lane == 0) { smx[warp] = mx; sai[warp] = ai; }
        __syncthreads();
        if (t == 0) {
            for (int w = 1; w < 8; ++w)
                if (smx[w] > smx[0] || (smx[w] == smx[0] && sai[w] < sai[0])) {
                    smx[0] = smx[w]; sai[0] = sai[w];
                }
        }
        __syncthreads();
        const float MX = smx[0];
        const int   AI = sai[0];

        float4 e;
        e.x = expf(v.x - MX); e.y = expf(v.y - MX);
        e.z = expf(v.z - MX); e.w = expf(v.w - MX);
        float s = e.x + e.y + e.z + e.w;
#pragma unroll
        for (int off = 16; off > 0; off >>= 1) s += __shfl_down_sync(full, s, off);
        if (lane == 0) ssum[warp] = s;
        __syncthreads();
        if (t == 0) {
            float tot = 0.f;
            for (int w = 0; w < 8; ++w) tot += ssum[w];
            ssum[0] = tot;
        }
        __syncthreads();
        const float inv = 1.f / ssum[0];

        float y0 = (t*4+0 == AI) ? e.x*inv : -e.x*inv;
        float y1 = (t*4+1 == AI) ? e.y*inv : -e.y*inv;
        float y2 = (t*4+2 == AI) ? e.z*inv : -e.z*inv;
        float y3 = (t*4+3 == AI) ? e.w*inv : -e.w*inv;

        mAcc[0] += y0 * v.x; mAcc[1] += y1 * v.y;
        mAcc[2] += y2 * v.z; mAcc[3] += y3 * v.w;

        // f16 split + smem store
        __half h0 = __float2half_rn(y0), h1 = __float2half_rn(y1);
        __half h2 = __float2half_rn(y2), h3 = __float2half_rn(y3);
        __half l0 = __float2half_rn(y0 - __half2float(h0));
        __half l1 = __float2half_rn(y1 - __half2float(h1));
        __half l2 = __float2half_rn(y2 - __half2float(h2));
        __half l3 = __float2half_rn(y3 - __half2float(h3));
        uint16_t* ph = &snh[r][t*4];
        uint16_t* pl = &snl[r][t*4];
        ph[0] = __half_as_ushort(h0); ph[1] = __half_as_ushort(h1);
        ph[2] = __half_as_ushort(h2); ph[3] = __half_as_ushort(h3);
        pl[0] = __half_as_ushort(l0); pl[1] = __half_as_ushort(l1);
        pl[2] = __half_as_ushort(l2); pl[3] = __half_as_ushort(l3);
        __syncthreads();
    }

    // m-partials (fp32, deterministic)
    reinterpret_cast<float4*>(&g_P[(size_t)blockIdx.x * OUTD])[t] =
        make_float4(mAcc[0], mAcc[1], mAcc[2], mAcc[3]);

    // transposed writes: 16 b's per o = 32 B = 2 x uint4
#pragma unroll
    for (int k = 0; k < 4; ++k) {
        const int o = t + k * 256;
        uint16_t vh[RPB], vl[RPB];
#pragma unroll
        for (int r = 0; r < RPB; ++r) { vh[r] = snh[r][o]; vl[r] = snl[r][o]; }
        uint4* dsth = reinterpret_cast<uint4*>(&ynTh[(size_t)o * BSZ + b0]);
        uint4* dstl = reinterpret_cast<uint4*>(&ynTl[(size_t)o * BSZ + b0]);
        dsth[0] = *reinterpret_cast<uint4*>(&vh[0]);
        dsth[1] = *reinterpret_cast<uint4*>(&vh[8]);
        dstl[0] = *reinterpret_cast<uint4*>(&vl[0]);
        dstl[1] = *reinterpret_cast<uint4*>(&vl[8]);
    }
}

// ============================================================
// m[o] = mean over NCHUNK partials / BSZ
// ============================================================
__global__ __launch_bounds__(256) void m_final_kernel()
{
    const int o = blockIdx.x * 256 + threadIdx.x;
    float acc = 0.f;
    for (int c = 0; c < NCHUNK; ++c) acc += g_P[c * OUTD + o];
    g_m[o] = acc * (1.f / (float)BSZ);
}

// ============================================================
// out[o,i] = rate[o] * (sum_s S[s][o,i]/B - m[o]*W[o,i])
// ============================================================
__global__ __launch_bounds__(256) void epilogue_kernel(
    const float* __restrict__ W, float* __restrict__ out)
{
    const int o = blockIdx.x;
    const int t = threadIdx.x;
    const float m = g_m[o];
    const float r = g_rate[o];
    float4 wv = reinterpret_cast<const float4*>(&W[(size_t)o * IND])[t];
    float4 s = make_float4(0.f, 0.f, 0.f, 0.f);
#pragma unroll
    for (int sp = 0; sp < NSPLIT; ++sp) {
        float4 p = reinterpret_cast<const float4*>(
            &g_S[(size_t)sp * OUTD * IND + (size_t)o * IND])[t];
        s.x += p.x; s.y += p.y; s.z += p.z; s.w += p.w;
    }
    const float invB = 1.f / (float)BSZ;
    float4 ov;
    ov.x = r * (s.x * invB - m * wv.x);
    ov.y = r * (s.y * invB - m * wv.y);
    ov.z = r * (s.z * invB - m * wv.z);
    ov.w = r * (s.w * invB - m * wv.w);
    reinterpret_cast<float4*>(&out[(size_t)o * IND])[t] = ov;
}

// ============================================================
extern "C" void kernel_launch(void* const* d_in, const int* in_sizes, int n_in,
                              void* d_out, int out_size)
{
    const float* x = (const float*)d_in[0];   // [8192, 1024]
    const float* W = (const float*)d_in[1];   // [1024, 1024]
    const float* b = (const float*)d_in[2];   // [1024]
    float* out = (float*)d_out;               // [1024, 1024]

    cudaFuncSetAttribute(gemm_bf16v5_kernel,
                         cudaFuncAttributeMaxDynamicSharedMemorySize, SMEM_BYTES);
    cudaFuncSetAttribute(gemm_f16_2p_kernel,
                         cudaFuncAttributeMaxDynamicSharedMemorySize, SMEM2_BYTES);

    float*    g_u_p;    cudaGetSymbolAddress((void**)&g_u_p,    g_u);
    float*    g_S_p;    cudaGetSymbolAddress((void**)&g_S_p,    g_S);
    uint16_t* g_xh_p;   cudaGetSymbolAddress((void**)&g_xh_p,   g_xh);
    uint16_t* g_xl_p;   cudaGetSymbolAddress((void**)&g_xl_p,   g_xl);
    uint16_t* g_Wh_p;   cudaGetSymbolAddress((void**)&g_Wh_p,   g_Wh);
    uint16_t* g_Wl_p;   cudaGetSymbolAddress((void**)&g_Wl_p,   g_Wl);
    uint16_t* g_xTh_p;  cudaGetSymbolAddress((void**)&g_xTh_p,  g_xTh);
    uint16_t* g_ynTh_p; cudaGetSymbolAddress((void**)&g_ynTh_p, g_ynTh);
    uint16_t* g_ynTl_p; cudaGetSymbolAddress((void**)&g_ynTl_p, g_ynTl);

    // fused prep: x -> bf16 hi/lo + x^T f16 ; W -> bf16 hi/lo + rate
    xprep_kernel<<<dim3(IND/32, BSZ/32), dim3(32, 8)>>>(
        x, g_xh_p, g_xl_p, g_xTh_p, BSZ, IND);
    wprep_kernel<<<OUTD, 256>>>(W, g_Wh_p, g_Wl_p);

    // u = x @ W^T + b  (bf16x3)
    gemm_bf16v5_kernel<<<dim3(OUTD/BN, BSZ/BM, 1), NTHREADS, SMEM_BYTES>>>(
        g_xh_p, g_xl_p, IND, g_Wh_p, g_Wl_p, IND,
        0, g_u_p, OUTD, 0, b, IND / BK);
    // fused: softmax + negate + yn^T f16 hi/lo + m-partials
    softmax_fused_kernel<<<BSZ/RPB, 256>>>(g_ynTh_p, g_ynTl_p);
    m_final_kernel<<<OUTD/256, 256>>>();
    // S[z] = yn^T @ x partials  (f16 2-pass, split-K = 4, 4-slot ring)
    gemm_f16_2p_kernel<<<dim3(IND/BN, OUTD/BM, NSPLIT), NTHREADS, SMEM2_BYTES>>>(
        g_ynTh_p, g_ynTl_p, BSZ, g_xTh_p, BSZ,
        BSZ/NSPLIT, g_S_p, IND, (size_t)OUTD * IND, (BSZ/NSPLIT) / BK);
    // out = rate * (sum S / B - m*W)
    epilogue_kernel<<<OUTD, 256>>>(W, out);
}

// round 15
// speedup vs baseline: 1.0529x; 1.0529x over previous
#include <cuda_runtime.h>
#include <cuda_fp16.h>
#include <cstdint>
#include <math.h>

#define BSZ   8192
#define IND   1024
#define OUTD  1024
#define NSPLIT 4
#define RPB    16                    // rows per fused-softmax block
#define NCHUNK (BSZ / 2)             // per-warp m-partial chunks (2 rows/warp)
#define NSLICE 32                    // m reduction slices

// ---- scratch (static device globals; no dynamic allocation) ----
__device__ float    g_u  [(size_t)BSZ * OUTD];           // 32 MB
__device__ float    g_P  [(size_t)NCHUNK * OUTD];        // 16 MB
__device__ float    g_P2 [NSLICE * OUTD];
__device__ float    g_m  [OUTD];
__device__ float    g_rate[OUTD];
__device__ float    g_S  [(size_t)NSPLIT * OUTD * IND];  // 16 MB
// GEMM1 operands: bf16 hi/lo (K-major)
__device__ uint16_t g_xh [(size_t)BSZ * IND];
__device__ uint16_t g_xl [(size_t)BSZ * IND];
__device__ uint16_t g_Wh [(size_t)OUTD * IND];
__device__ uint16_t g_Wl [(size_t)OUTD * IND];
// GEMM2 operands: f16 (x^T single, yn^T hi/lo)
__device__ uint16_t g_xTh [(size_t)IND * BSZ];
__device__ uint16_t g_ynTh[(size_t)OUTD * BSZ];
__device__ uint16_t g_ynTl[(size_t)OUTD * BSZ];

// ============================================================
// helpers
// ============================================================
__device__ __forceinline__ uint32_t bf16x2_rn(float hi, float lo) {
    uint32_t r;
    asm("cvt.rn.bf16x2.f32 %0, %1, %2;" : "=r"(r) : "f"(hi), "f"(lo));
    return r;
}
__device__ __forceinline__ void mma_bf16_k16(float c[4], const uint32_t a[4],
                                             const uint32_t b[2])
{
    asm volatile(
        "mma.sync.aligned.m16n8k16.row.col.f32.bf16.bf16.f32 "
        "{%0,%1,%2,%3}, {%4,%5,%6,%7}, {%8,%9}, {%0,%1,%2,%3};\n"
        : "+f"(c[0]), "+f"(c[1]), "+f"(c[2]), "+f"(c[3])
        : "r"(a[0]), "r"(a[1]), "r"(a[2]), "r"(a[3]),
          "r"(b[0]), "r"(b[1]));
}
__device__ __forceinline__ void mma_f16_k16(float c[4], const uint32_t a[4],
                                            const uint32_t b[2])
{
    asm volatile(
        "mma.sync.aligned.m16n8k16.row.col.f32.f16.f16.f32 "
        "{%0,%1,%2,%3}, {%4,%5,%6,%7}, {%8,%9}, {%0,%1,%2,%3};\n"
        : "+f"(c[0]), "+f"(c[1]), "+f"(c[2]), "+f"(c[3])
        : "r"(a[0]), "r"(a[1]), "r"(a[2]), "r"(a[3]),
          "r"(b[0]), "r"(b[1]));
}
__device__ __forceinline__ void ldsm_x4(uint32_t r[4], uint32_t addr) {
    asm volatile("ldmatrix.sync.aligned.m8n8.x4.shared.b16 {%0,%1,%2,%3}, [%4];"
        : "=r"(r[0]), "=r"(r[1]), "=r"(r[2]), "=r"(r[3]) : "r"(addr));
}
#define CP_ASYNC16(saddr, gptr) \
    asm volatile("cp.async.cg.shared.global [%0], [%1], 16;" \
        :: "r"(saddr), "l"(gptr))
// .noinc: arrive WITHOUT bumping expected-count (barrier inited to NTHREADS).
#define CP_MBAR_ARRIVE(mbar) \
    asm volatile("cp.async.mbarrier.arrive.noinc.shared::cta.b64 [%0];" \
        :: "r"((uint32_t)(mbar)) : "memory")
#define MBARRIER_INIT(mbar, cnt) \
    asm volatile("mbarrier.init.shared.b64 [%0], %1;" \
        :: "r"((uint32_t)(mbar)), "r"((uint32_t)(cnt)) : "memory")
#define MBARRIER_ARRIVE(mbar) \
    asm volatile("mbarrier.arrive.shared::cta.b64 _, [%0];" \
        :: "r"((uint32_t)(mbar)) : "memory")
#define MBARRIER_WAIT_PARITY(mbar, parity) do {                                   \
    uint32_t _m = (uint32_t)(mbar); uint32_t _p = (uint32_t)(parity);             \
    uint32_t _done;                                                               \
    asm volatile("{\n\t.reg .pred p;\n\t"                                         \
        "mbarrier.try_wait.parity.acquire.cta.shared::cta.b64 p, [%1], %2;\n\t"   \
        "selp.b32 %0, 1, 0, p;\n\t}" : "=r"(_done) : "r"(_m), "r"(_p) : "memory");\
    if (!_done) {                                                                 \
        asm volatile("{\n\t.reg .pred P1;\n\t"                                    \
            "WL_%=:\n\t"                                                          \
            "mbarrier.try_wait.parity.acquire.cta.shared::cta.b64 P1, [%0], %1, 0x989680;\n\t" \
            "@P1 bra.uni WD_%=;\n\t"                                              \
            "bra.uni WL_%=;\n\t"                                                  \
            "WD_%=:\n\t}" :: "r"(_m), "r"(_p) : "memory");                        \
    }                                                                             \
} while (0)

// Common geometry
#define BK      32
#define BM      256
#define BN      128
#define STRIDE  40
#define NTHREADS 512

// ---- GEMM1 (bf16 3-pass) stage layout, 3-slot ring ----
#define NSTAGE1 3
#define SM_AH   0
#define SM_AL   (BM * STRIDE * 2)                          // 20480
#define SM_BH   (2 * BM * STRIDE * 2)                      // 40960
#define SM_BL   (2 * BM * STRIDE * 2 + BN * STRIDE * 2)    // 51200
#define STAGE_B (2 * BM * STRIDE * 2 + 2 * BN * STRIDE * 2) // 61440
#define SM_BARS (NSTAGE1 * STAGE_B)                        // 184320
#define SMEM_BYTES (SM_BARS + 64)

// ---- GEMM2 (f16 2-pass) stage layout: Ah, Al, Bh; 4-slot ring ----
#define NSTAGE2 4
#define P2_AH    0
#define P2_AL    (BM * STRIDE * 2)                         // 20480
#define P2_BH    (2 * BM * STRIDE * 2)                     // 40960
#define STAGE2_B (2 * BM * STRIDE * 2 + BN * STRIDE * 2)   // 51200
#define SM2_BARS (NSTAGE2 * STAGE2_B)                      // 204800
#define SMEM2_BYTES (SM2_BARS + 64)

// ============================================================
// fill helpers
// ============================================================
__device__ __forceinline__ void fill_stage3(
    uint32_t sbase, int t,
    const uint16_t* __restrict__ Ah, const uint16_t* __restrict__ Al, int lda,
    const uint16_t* __restrict__ Bh, const uint16_t* __restrict__ Bl, int ldb,
    int m0, int n0, int ks0)
{
#pragma unroll
    for (int i = 0; i < 2; ++i) {
        const int c   = t + 512 * i;
        const int row = c >> 2;
        const int c16 = c & 3;
        const size_t go = (size_t)(m0 + row) * lda + ks0 + c16 * 8;
        const uint32_t so = (uint32_t)((row * STRIDE + c16 * 8) * 2);
        CP_ASYNC16(sbase + SM_AH + so, Ah + go);
        CP_ASYNC16(sbase + SM_AL + so, Al + go);
    }
    {
        const int row = t >> 2;
        const int c16 = t & 3;
        const size_t go = (size_t)(n0 + row) * ldb + ks0 + c16 * 8;
        const uint32_t so = (uint32_t)((row * STRIDE + c16 * 8) * 2);
        CP_ASYNC16(sbase + SM_BH + so, Bh + go);
        CP_ASYNC16(sbase + SM_BL + so, Bl + go);
    }
}

__device__ __forceinline__ void fill_stage2(
    uint32_t sbase, int t,
    const uint16_t* __restrict__ Ah, const uint16_t* __restrict__ Al, int lda,
    const uint16_t* __restrict__ Bh, int ldb,
    int m0, int n0, int ks0)
{
#pragma unroll
    for (int i = 0; i < 2; ++i) {
        const int c   = t + 512 * i;
        const int row = c >> 2;
        const int c16 = c & 3;
        const size_t go = (size_t)(m0 + row) * lda + ks0 + c16 * 8;
        const uint32_t so = (uint32_t)((row * STRIDE + c16 * 8) * 2);
        CP_ASYNC16(sbase + P2_AH + so, Ah + go);
        CP_ASYNC16(sbase + P2_AL + so, Al + go);
    }
    {
        const int row = t >> 2;
        const int c16 = t & 3;
        const size_t go = (size_t)(n0 + row) * ldb + ks0 + c16 * 8;
        const uint32_t so = (uint32_t)((row * STRIDE + c16 * 8) * 2);
        CP_ASYNC16(sbase + P2_BH + so, Bh + go);
    }
}

// ============================================================
// GEMM1: bf16x3 mma.sync with mbarrier full/empty ring (R11 design).
// ============================================================
__global__ __launch_bounds__(NTHREADS, 1) void gemm_bf16v5_kernel(
    const uint16_t* __restrict__ Ah, const uint16_t* __restrict__ Al, int lda,
    const uint16_t* __restrict__ Bh, const uint16_t* __restrict__ Bl, int ldb,
    int kzstep, float* __restrict__ dstBase, int ldd, size_t zstride,
    const float* __restrict__ bias, int nstages)
{
    extern __shared__ uint16_t sm[];
    const uint32_t sbase0 = (uint32_t)__cvta_generic_to_shared(sm);
    const uint32_t barF = sbase0 + SM_BARS;
    const uint32_t barE = sbase0 + SM_BARS + NSTAGE1 * 8;

    const int t     = threadIdx.x;
    const int lane  = t & 31;
    const int warp  = t >> 5;
    const int warpM = warp & 3;
    const int warpN = warp >> 2;
    const int m0    = blockIdx.y * BM;
    const int n0    = blockIdx.x * BN;
    const int kbase = blockIdx.z * kzstep;
    float* dst = dstBase + (size_t)blockIdx.z * zstride;

    const int gr   = lane >> 2;
    const int la15 = lane & 15;
    const int lhi  = lane >> 4;

    uint32_t aoff[4], boff[2];
#pragma unroll
    for (int mt = 0; mt < 4; ++mt)
        aoff[mt] = (uint32_t)(((warpM * 64 + mt * 16 + la15) * STRIDE
                               + lhi * 8) * 2);
#pragma unroll
    for (int p = 0; p < 2; ++p)
        boff[p] = (uint32_t)(((warpN * 32 + p * 16 + lhi * 8 + (lane & 7))
                               * STRIDE + ((lane >> 3) & 1) * 8) * 2);

    if (t == 0) {
#pragma unroll
        for (int j = 0; j < NSTAGE1; ++j) {
            MBARRIER_INIT(barF + j * 8, NTHREADS);
            MBARRIER_INIT(barE + j * 8, NTHREADS);
        }
    }
    __syncthreads();

    float c[4][4][4];
#pragma unroll
    for (int mt = 0; mt < 4; ++mt)
#pragma unroll
        for (int nt = 0; nt < 4; ++nt)
#pragma unroll
            for (int e = 0; e < 4; ++e) c[mt][nt][e] = 0.f;

    fill_stage3(sbase0, t, Ah, Al, lda, Bh, Bl, ldb, m0, n0, kbase);
    CP_MBAR_ARRIVE(barF);

    int fs = 1, pslot = 1, pph = 0;
    int cslot = 0, cph = 0;

    for (int s = 0; s < nstages; ++s) {
        if (fs < nstages) {
            if (fs >= NSTAGE1)
                MBARRIER_WAIT_PARITY(barE + pslot * 8, pph ^ 1);
            fill_stage3(sbase0 + pslot * STAGE_B, t, Ah, Al, lda, Bh, Bl, ldb,
                        m0, n0, kbase + fs * BK);
            CP_MBAR_ARRIVE(barF + pslot * 8);
            ++fs;
            if (++pslot == NSTAGE1) { pslot = 0; pph ^= 1; }
        }

        MBARRIER_WAIT_PARITY(barF + cslot * 8, cph);
        const uint32_t sb  = sbase0 + cslot * STAGE_B;
        const uint32_t sAh = sb + SM_AH;
        const uint32_t sAl = sb + SM_AL;
        const uint32_t sBh = sb + SM_BH;
        const uint32_t sBl = sb + SM_BL;

#pragma unroll
        for (int ks = 0; ks < 2; ++ks) {
            const uint32_t ko = (uint32_t)(ks * 32);
            uint32_t ah[4][4], bb[4][2], t4[4];

#pragma unroll
            for (int mt = 0; mt < 4; ++mt)
                ldsm_x4(ah[mt], sAh + aoff[mt] + ko);
#pragma unroll
            for (int p = 0; p < 2; ++p) {
                ldsm_x4(t4, sBh + boff[p] + ko);
                bb[2*p][0] = t4[0]; bb[2*p][1] = t4[1];
                bb[2*p+1][0] = t4[2]; bb[2*p+1][1] = t4[3];
            }
#pragma unroll
            for (int mt = 0; mt < 4; ++mt)
#pragma unroll
                for (int nt = 0; nt < 4; ++nt)
                    mma_bf16_k16(c[mt][nt], ah[mt], bb[nt]);
            {
                uint32_t bl[4][2];
#pragma unroll
                for (int p = 0; p < 2; ++p) {
                    ldsm_x4(t4, sBl + boff[p] + ko);
                    bl[2*p][0] = t4[0]; bl[2*p][1] = t4[1];
                    bl[2*p+1][0] = t4[2]; bl[2*p+1][1] = t4[3];
                }
#pragma unroll
                for (int mt = 0; mt < 4; ++mt)
#pragma unroll
                    for (int nt = 0; nt < 4; ++nt)
                        mma_bf16_k16(c[mt][nt], ah[mt], bl[nt]);
            }
            {
                uint32_t al[4][4];
#pragma unroll
                for (int mt = 0; mt < 4; ++mt)
                    ldsm_x4(al[mt], sAl + aoff[mt] + ko);
                if (ks == 1)
                    MBARRIER_ARRIVE(barE + cslot * 8);
#pragma unroll
                for (int mt = 0; mt < 4; ++mt)
#pragma unroll
                    for (int nt = 0; nt < 4; ++nt)
                        mma_bf16_k16(c[mt][nt], al[mt], bb[nt]);
            }
        }
        if (++cslot == NSTAGE1) { cslot = 0; cph ^= 1; }
    }

#pragma unroll
    for (int mt = 0; mt < 4; ++mt) {
        const int r = m0 + warpM * 64 + mt * 16 + gr;
#pragma unroll
        for (int nt = 0; nt < 4; ++nt) {
            const int cc = n0 + warpN * 32 + nt * 8 + (lane & 3) * 2;
            float2 v0 = make_float2(c[mt][nt][0], c[mt][nt][1]);
            float2 v1 = make_float2(c[mt][nt][2], c[mt][nt][3]);
            if (bias) {
                const float b0 = __ldg(&bias[cc]);
                const float b1 = __ldg(&bias[cc + 1]);
                v0.x += b0; v0.y += b1;
                v1.x += b0; v1.y += b1;
            }
            *reinterpret_cast<float2*>(&dst[(size_t)r * ldd + cc])       = v0;
            *reinterpret_cast<float2*>(&dst[(size_t)(r + 8) * ldd + cc]) = v1;
        }
    }
}

// ============================================================
// GEMM2: f16 2-pass, 4-slot ring (R13 design).
// ============================================================
__global__ __launch_bounds__(NTHREADS, 1) void gemm_f16_2p_kernel(
    const uint16_t* __restrict__ Ah, const uint16_t* __restrict__ Al, int lda,
    const uint16_t* __restrict__ Bh, int ldb,
    int kzstep, float* __restrict__ dstBase, int ldd, size_t zstride,
    int nstages)
{
    extern __shared__ uint16_t sm[];
    const uint32_t sbase0 = (uint32_t)__cvta_generic_to_shared(sm);
    const uint32_t barF = sbase0 + SM2_BARS;
    const uint32_t barE = sbase0 + SM2_BARS + NSTAGE2 * 8;

    const int t     = threadIdx.x;
    const int lane  = t & 31;
    const int warp  = t >> 5;
    const int warpM = warp & 3;
    const int warpN = warp >> 2;
    const int m0    = blockIdx.y * BM;
    const int n0    = blockIdx.x * BN;
    const int kbase = blockIdx.z * kzstep;
    float* dst = dstBase + (size_t)blockIdx.z * zstride;

    const int gr   = lane >> 2;
    const int la15 = lane & 15;
    const int lhi  = lane >> 4;

    uint32_t aoff[4], boff[2];
#pragma unroll
    for (int mt = 0; mt < 4; ++mt)
        aoff[mt] = (uint32_t)(((warpM * 64 + mt * 16 + la15) * STRIDE
                               + lhi * 8) * 2);
#pragma unroll
    for (int p = 0; p < 2; ++p)
        boff[p] = (uint32_t)(((warpN * 32 + p * 16 + lhi * 8 + (lane & 7))
                               * STRIDE + ((lane >> 3) & 1) * 8) * 2);

    if (t == 0) {
#pragma unroll
        for (int j = 0; j < NSTAGE2; ++j) {
            MBARRIER_INIT(barF + j * 8, NTHREADS);
            MBARRIER_INIT(barE + j * 8, NTHREADS);
        }
    }
    __syncthreads();

    float c[4][4][4];
#pragma unroll
    for (int mt = 0; mt < 4; ++mt)
#pragma unroll
        for (int nt = 0; nt < 4; ++nt)
#pragma unroll
            for (int e = 0; e < 4; ++e) c[mt][nt][e] = 0.f;

    fill_stage2(sbase0, t, Ah, Al, lda, Bh, ldb, m0, n0, kbase);
    CP_MBAR_ARRIVE(barF);

    int fs = 1, pslot = 1, pph = 0;
    int cslot = 0, cph = 0;

    for (int s = 0; s < nstages; ++s) {
        if (fs < nstages) {
            if (fs >= NSTAGE2)
                MBARRIER_WAIT_PARITY(barE + pslot * 8, pph ^ 1);
            fill_stage2(sbase0 + pslot * STAGE2_B, t, Ah, Al, lda, Bh, ldb,
                        m0, n0, kbase + fs * BK);
            CP_MBAR_ARRIVE(barF + pslot * 8);
            ++fs;
            if (++pslot == NSTAGE2) { pslot = 0; pph ^= 1; }
        }

        MBARRIER_WAIT_PARITY(barF + cslot * 8, cph);
        const uint32_t sb  = sbase0 + cslot * STAGE2_B;
        const uint32_t sAh = sb + P2_AH;
        const uint32_t sAl = sb + P2_AL;
        const uint32_t sBh = sb + P2_BH;

#pragma unroll
        for (int ks = 0; ks < 2; ++ks) {
            const uint32_t ko = (uint32_t)(ks * 32);
            uint32_t ah[4][4], bb[4][2], t4[4];

#pragma unroll
            for (int mt = 0; mt < 4; ++mt)
                ldsm_x4(ah[mt], sAh + aoff[mt] + ko);
#pragma unroll
            for (int p = 0; p < 2; ++p) {
                ldsm_x4(t4, sBh + boff[p] + ko);
                bb[2*p][0] = t4[0]; bb[2*p][1] = t4[1];
                bb[2*p+1][0] = t4[2]; bb[2*p+1][1] = t4[3];
            }
#pragma unroll
            for (int mt = 0; mt < 4; ++mt)
#pragma unroll
                for (int nt = 0; nt < 4; ++nt)
                    mma_f16_k16(c[mt][nt], ah[mt], bb[nt]);
            {
                uint32_t al[4][4];
#pragma unroll
                for (int mt = 0; mt < 4; ++mt)
                    ldsm_x4(al[mt], sAl + aoff[mt] + ko);
                if (ks == 1)
                    MBARRIER_ARRIVE(barE + cslot * 8);
#pragma unroll
                for (int mt = 0; mt < 4; ++mt)
#pragma unroll
                    for (int nt = 0; nt < 4; ++nt)
                        mma_f16_k16(c[mt][nt], al[mt], bb[nt]);
            }
        }
        if (++cslot == NSTAGE2) { cslot = 0; cph ^= 1; }
    }

#pragma unroll
    for (int mt = 0; mt < 4; ++mt) {
        const int r = m0 + warpM * 64 + mt * 16 + gr;
#pragma unroll
        for (int nt = 0; nt < 4; ++nt) {
            const int cc = n0 + warpN * 32 + nt * 8 + (lane & 3) * 2;
            *reinterpret_cast<float2*>(&dst[(size_t)r * ldd + cc]) =
                make_float2(c[mt][nt][0], c[mt][nt][1]);
            *reinterpret_cast<float2*>(&dst[(size_t)(r + 8) * ldd + cc]) =
                make_float2(c[mt][nt][2], c[mt][nt][3]);
        }
    }
}

// ============================================================
// Fused x prep: read x once -> bf16 hi/lo row-major + x^T f16
// ============================================================
__global__ __launch_bounds__(256) void xprep_kernel(
    const float* __restrict__ src, uint16_t* __restrict__ dh,
    uint16_t* __restrict__ dl, uint16_t* __restrict__ dT, int R, int C)
{
    __shared__ float tile[32][33];
    const int c0 = blockIdx.x * 32;
    const int r0 = blockIdx.y * 32;
    const int tx = threadIdx.x, ty = threadIdx.y;
#pragma unroll
    for (int i = 0; i < 4; ++i) {
        const size_t o = (size_t)(r0 + ty + i*8) * C + c0 + tx;
        float v = src[o];
        tile[ty + i*8][tx] = v;
        uint32_t u = __float_as_uint(v);
        float lo = v - __uint_as_float(u & 0xFFFF0000u);
        dh[o] = (uint16_t)(u >> 16);
        dl[o] = (uint16_t)(bf16x2_rn(lo, lo) & 0xFFFF);
    }
    __syncthreads();
#pragma unroll
    for (int i = 0; i < 4; ++i) {
        __half h = __float2half_rn(tile[tx][ty + i*8]);
        dT[(size_t)(c0 + ty + i*8) * R + r0 + tx] = __half_as_ushort(h);
    }
}

// ============================================================
// Fused W prep: read W once -> bf16 hi/lo + adaptive rate
// ============================================================
__global__ __launch_bounds__(256) void wprep_kernel(
    const float* __restrict__ W, uint16_t* __restrict__ dh,
    uint16_t* __restrict__ dl)
{
    const int o = blockIdx.x;
    const int t = threadIdx.x;
    const unsigned full = 0xffffffffu;
    float4 v = reinterpret_cast<const float4*>(&W[(size_t)o * IND])[t];

    uint32_t x0 = __float_as_uint(v.x), x1 = __float_as_uint(v.y);
    uint32_t x2 = __float_as_uint(v.z), x3 = __float_as_uint(v.w);
    float l0 = v.x - __uint_as_float(x0 & 0xFFFF0000u);
    float l1 = v.y - __uint_as_float(x1 & 0xFFFF0000u);
    float l2 = v.z - __uint_as_float(x2 & 0xFFFF0000u);
    float l3 = v.w - __uint_as_float(x3 & 0xFFFF0000u);
    reinterpret_cast<uint2*>(dh)[(size_t)o * (IND/4) + t] =
        make_uint2(__byte_perm(x0, x1, 0x7632), __byte_perm(x2, x3, 0x7632));
    reinterpret_cast<uint2*>(dl)[(size_t)o * (IND/4) + t] =
        make_uint2(bf16x2_rn(l1, l0), bf16x2_rn(l3, l2));

    float s = v.x*v.x + v.y*v.y + v.z*v.z + v.w*v.w;
#pragma unroll
    for (int off = 16; off > 0; off >>= 1) s += __shfl_down_sync(full, s, off);
    __shared__ float ssum[8];
    const int warp = t >> 5, lane = t & 31;
    if (lane == 0) ssum[warp] = s;
    __syncthreads();
    if (t == 0) {
        float tot = 0.f;
        for (int w2 = 0; w2 < 8; ++w2) tot += ssum[w2];
        g_rate[o] = 1e-3f * sqrtf(fabsf(1.f - sqrtf(tot)));
    }
}

// ============================================================
// Warp-autonomous fused softmax: each warp owns 2 full rows
// (32 elems/lane). All reductions via shfl.bfly; ONE block sync total.
// Emits yn^T f16 hi/lo (transposed) + per-warp m-partials.
// ============================================================
__global__ __launch_bounds__(256) void softmax_fused_kernel(
    uint16_t* __restrict__ ynTh, uint16_t* __restrict__ ynTl)
{
    __shared__ uint16_t snh[RPB][1032];
    __shared__ uint16_t snl[RPB][1032];

    const int t = threadIdx.x;
    const int warp = t >> 5, lane = t & 31;
    const int b0 = blockIdx.x * RPB;
    const unsigned full = 0xffffffffu;

    float mAcc[32];
#pragma unroll
    for (int j = 0; j < 32; ++j) mAcc[j] = 0.f;

#pragma unroll
    for (int rr = 0; rr < 2; ++rr) {
        const int r = warp * 2 + rr;           // 0..15
        const size_t rowoff = (size_t)(b0 + r) * OUTD;

        float4 v[8];
#pragma unroll
        for (int j = 0; j < 8; ++j)
            v[j] = *reinterpret_cast<const float4*>(
                &g_u[rowoff + j * 128 + lane * 4]);

        // warp argmax (first occurrence)
        float mx = v[0].x; int ai = lane * 4;
#pragma unroll
        for (int j = 0; j < 8; ++j) {
            const int base = j * 128 + lane * 4;
            if (v[j].x > mx) { mx = v[j].x; ai = base; }
            if (v[j].y > mx) { mx = v[j].y; ai = base + 1; }
            if (v[j].z > mx) { mx = v[j].z; ai = base + 2; }
            if (v[j].w > mx) { mx = v[j].w; ai = base + 3; }
        }
#pragma unroll
        for (int off = 16; off > 0; off >>= 1) {
            float omx = __shfl_xor_sync(full, mx, off);
            int   oai = __shfl_xor_sync(full, ai, off);
            if (omx > mx || (omx == mx && oai < ai)) { mx = omx; ai = oai; }
        }
        const float MX = mx;
        const int   AI = ai;

        // exp + sum
        float e[32];
        float s = 0.f;
#pragma unroll
        for (int j = 0; j < 8; ++j) {
            e[j*4+0] = expf(v[j].x - MX);
            e[j*4+1] = expf(v[j].y - MX);
            e[j*4+2] = expf(v[j].z - MX);
            e[j*4+3] = expf(v[j].w - MX);
            s += e[j*4+0] + e[j*4+1] + e[j*4+2] + e[j*4+3];
        }
#pragma unroll
        for (int off = 16; off > 0; off >>= 1)
            s += __shfl_xor_sync(full, s, off);
        const float inv = 1.f / s;

        // yn, m-acc, f16 split, smem store
#pragma unroll
        for (int j = 0; j < 8; ++j) {
            const int base = j * 128 + lane * 4;
            const float* vf = reinterpret_cast<const float*>(&v[j]);
            uint16_t hh[4], ll[4];
#pragma unroll
            for (int k = 0; k < 4; ++k) {
                float y = (base + k == AI) ? e[j*4+k] * inv : -e[j*4+k] * inv;
                mAcc[j*4+k] += y * vf[k];
                __half h = __float2half_rn(y);
                __half l = __float2half_rn(y - __half2float(h));
                hh[k] = __half_as_ushort(h);
                ll[k] = __half_as_ushort(l);
            }
            *reinterpret_cast<uint2*>(&snh[r][base]) =
                *reinterpret_cast<uint2*>(hh);
            *reinterpret_cast<uint2*>(&snl[r][base]) =
                *reinterpret_cast<uint2*>(ll);
        }
    }

    // per-warp m-partials: chunk = blockIdx*8 + warp
    {
        float* dst = &g_P[(size_t)(blockIdx.x * 8 + warp) * OUTD];
#pragma unroll
        for (int j = 0; j < 8; ++j)
            *reinterpret_cast<float4*>(&dst[j * 128 + lane * 4]) =
                make_float4(mAcc[j*4], mAcc[j*4+1], mAcc[j*4+2], mAcc[j*4+3]);
    }

    __syncthreads();   // all rows staged

    // transposed writes: 16 b's per o = 32 B = 2 x uint4 (per hi/lo)
#pragma unroll
    for (int k = 0; k < 4; ++k) {
        const int o = t + k * 256;
        uint16_t vh[RPB], vl[RPB];
#pragma unroll
        for (int r = 0; r < RPB; ++r) { vh[r] = snh[r][o]; vl[r] = snl[r][o]; }
        uint4* dsth = reinterpret_cast<uint4*>(&ynTh[(size_t)o * BSZ + b0]);
        uint4* dstl = reinterpret_cast<uint4*>(&ynTl[(size_t)o * BSZ + b0]);
        dsth[0] = *reinterpret_cast<uint4*>(&vh[0]);
        dsth[1] = *reinterpret_cast<uint4*>(&vh[8]);
        dstl[0] = *reinterpret_cast<uint4*>(&vl[0]);
        dstl[1] = *reinterpret_cast<uint4*>(&vl[8]);
    }
}

// ============================================================
// m reduction: stage 1 (128 chunks per slice), stage 2 (32 slices)
// ============================================================
__global__ __launch_bounds__(256) void mpart_kernel()
{
    const int o = blockIdx.x * 256 + threadIdx.x;
    const int c0 = blockIdx.y * (NCHUNK / NSLICE);
    float acc = 0.f;
#pragma unroll 4
    for (int c = 0; c < NCHUNK / NSLICE; ++c)
        acc += g_P[(size_t)(c0 + c) * OUTD + o];
    g_P2[blockIdx.y * OUTD + o] = acc;
}

__global__ __launch_bounds__(256) void m_final_kernel()
{
    const int o = blockIdx.x * 256 + threadIdx.x;
    float acc = 0.f;
#pragma unroll
    for (int c = 0; c < NSLICE; ++c) acc += g_P2[c * OUTD + o];
    g_m[o] = acc * (1.f / (float)BSZ);
}

// ============================================================
// out[o,i] = rate[o] * (sum_s S[s][o,i]/B - m[o]*W[o,i])
// ============================================================
__global__ __launch_bounds__(256) void epilogue_kernel(
    const float* __restrict__ W, float* __restrict__ out)
{
    const int o = blockIdx.x;
    const int t = threadIdx.x;
    const float m = g_m[o];
    const float r = g_rate[o];
    float4 wv = reinterpret_cast<const float4*>(&W[(size_t)o * IND])[t];
    float4 s = make_float4(0.f, 0.f, 0.f, 0.f);
#pragma unroll
    for (int sp = 0; sp < NSPLIT; ++sp) {
        float4 p = reinterpret_cast<const float4*>(
            &g_S[(size_t)sp * OUTD * IND + (size_t)o * IND])[t];
        s.x += p.x; s.y += p.y; s.z += p.z; s.w += p.w;
    }
    const float invB = 1.f / (float)BSZ;
    float4 ov;
    ov.x = r * (s.x * invB - m * wv.x);
    ov.y = r * (s.y * invB - m * wv.y);
    ov.z = r * (s.z * invB - m * wv.z);
    ov.w = r * (s.w * invB - m * wv.w);
    reinterpret_cast<float4*>(&out[(size_t)o * IND])[t] = ov;
}

// ============================================================
extern "C" void kernel_launch(void* const* d_in, const int* in_sizes, int n_in,
                              void* d_out, int out_size)
{
    const float* x = (const float*)d_in[0];   // [8192, 1024]
    const float* W = (const float*)d_in[1];   // [1024, 1024]
    const float* b = (const float*)d_in[2];   // [1024]
    float* out = (float*)d_out;               // [1024, 1024]

    cudaFuncSetAttribute(gemm_bf16v5_kernel,
                         cudaFuncAttributeMaxDynamicSharedMemorySize, SMEM_BYTES);
    cudaFuncSetAttribute(gemm_f16_2p_kernel,
                         cudaFuncAttributeMaxDynamicSharedMemorySize, SMEM2_BYTES);

    float*    g_u_p;    cudaGetSymbolAddress((void**)&g_u_p,    g_u);
    float*    g_S_p;    cudaGetSymbolAddress((void**)&g_S_p,    g_S);
    uint16_t* g_xh_p;   cudaGetSymbolAddress((void**)&g_xh_p,   g_xh);
    uint16_t* g_xl_p;   cudaGetSymbolAddress((void**)&g_xl_p,   g_xl);
    uint16_t* g_Wh_p;   cudaGetSymbolAddress((void**)&g_Wh_p,   g_Wh);
    uint16_t* g_Wl_p;   cudaGetSymbolAddress((void**)&g_Wl_p,   g_Wl);
    uint16_t* g_xTh_p;  cudaGetSymbolAddress((void**)&g_xTh_p,  g_xTh);
    uint16_t* g_ynTh_p; cudaGetSymbolAddress((void**)&g_ynTh_p, g_ynTh);
    uint16_t* g_ynTl_p; cudaGetSymbolAddress((void**)&g_ynTl_p, g_ynTl);

    // fused prep: x -> bf16 hi/lo + x^T f16 ; W -> bf16 hi/lo + rate
    xprep_kernel<<<dim3(IND/32, BSZ/32), dim3(32, 8)>>>(
        x, g_xh_p, g_xl_p, g_xTh_p, BSZ, IND);
    wprep_kernel<<<OUTD, 256>>>(W, g_Wh_p, g_Wl_p);

    // u = x @ W^T + b  (bf16x3)
    gemm_bf16v5_kernel<<<dim3(OUTD/BN, BSZ/BM, 1), NTHREADS, SMEM_BYTES>>>(
        g_xh_p, g_xl_p, IND, g_Wh_p, g_Wl_p, IND,
        0, g_u_p, OUTD, 0, b, IND / BK);
    // warp-autonomous fused softmax + yn^T f16 hi/lo + m-partials
    softmax_fused_kernel<<<BSZ/RPB, 256>>>(g_ynTh_p, g_ynTl_p);
    mpart_kernel<<<dim3(OUTD/256, NSLICE), 256>>>();
    m_final_kernel<<<OUTD/256, 256>>>();
    // S[z] = yn^T @ x partials  (f16 2-pass, split-K = 4, 4-slot ring)
    gemm_f16_2p_kernel<<<dim3(IND/BN, OUTD/BM, NSPLIT), NTHREADS, SMEM2_BYTES>>>(
        g_ynTh_p, g_ynTl_p, BSZ, g_xTh_p, BSZ,
        BSZ/NSPLIT, g_S_p, IND, (size_t)OUTD * IND, (BSZ/NSPLIT) / BK);
    // out = rate * (sum S / B - m*W)
    epilogue_kernel<<<OUTD, 256>>>(W, out);
}